// round 12
// baseline (speedup 1.0000x reference)
#include <cuda_runtime.h>
#include <cuda_fp16.h>
#include <cstdint>

#define N_LIC 40000
#define N_EMP 80000
#define N_CON 60000
#define D_LIC 256
#define D_EMP 128
#define D_CON 192
#define HDIM  256
#define E_P   1280000
#define E_Q   640000
#define KTOT  576    // 128 + 192 + 256
#define NCHUNK 18    // KTOT / 32

#define CAP_P 96     // max degree, relation p (mean 32)
#define CAP_Q 64     // max degree, relation q (mean 16)

// ---------------- scratch (static device globals; no runtime alloc) --------
__device__ uint32_t g_Ax[(size_t)N_LIC * 128];     // x_lic fp16 packed (A cols 160-288)
__device__ uint32_t g_Wh[(size_t)HDIM * 288];      // W^T packed fp16x2 (row stride 288)
__device__ uint32_t g_xe[(size_t)N_EMP * 64];      // x_emp fp16 packed (20MB)
__device__ uint32_t g_xc[(size_t)N_CON * 96];      // x_con fp16 packed (23MB)
__device__ float    g_b[HDIM];
__device__ int      g_cnt_p[N_LIC];                // zero-init; self-cleaned by gemm gather
__device__ int      g_cnt_q[N_LIC];
__device__ int      g_col_p[(size_t)N_LIC * CAP_P];
__device__ int      g_col_q[(size_t)N_LIC * CAP_Q];

// ---------------- helpers ------------------------------------------------------
__device__ __forceinline__ uint32_t pack_h(float x, float y) {
    __half2 h = __floats2half2_rn(x, y);
    return *(uint32_t*)&h;
}
__device__ __forceinline__ float2 unpack_h(uint32_t u) {
    return __half22float2(*(__half2*)&u);
}
__device__ __forceinline__ uint32_t smem_u32(const void* p) {
    uint32_t a;
    asm("{ .reg .u64 t; cvta.to.shared.u64 t, %1; cvt.u32.u64 %0, t; }" : "=r"(a) : "l"(p));
    return a;
}
__device__ __forceinline__ void cp16(uint32_t dst, const void* src) {
    asm volatile("cp.async.cg.shared.global [%0], [%1], 16;" :: "r"(dst), "l"(src));
}
__device__ __forceinline__ void ldsm4(uint32_t addr, uint32_t* r) {
    asm volatile("ldmatrix.sync.aligned.m8n8.x4.shared.b16 {%0,%1,%2,%3}, [%4];"
                 : "=r"(r[0]), "=r"(r[1]), "=r"(r[2]), "=r"(r[3]) : "r"(addr));
}
__device__ __forceinline__ void mma_f16(float* c, const uint32_t* a, uint32_t b0, uint32_t b1) {
    asm volatile(
        "mma.sync.aligned.m16n8k16.row.col.f32.f16.f16.f32 "
        "{%0,%1,%2,%3}, {%4,%5,%6,%7}, {%8,%9}, {%0,%1,%2,%3};"
        : "+f"(c[0]), "+f"(c[1]), "+f"(c[2]), "+f"(c[3])
        : "r"(a[0]), "r"(a[1]), "r"(a[2]), "r"(a[3]), "r"(b0), "r"(b1));
}

// ---------------- K1: fused fill + conv + xsplit + weight-prep ------------------
#define R_FILL    ((E_P + E_Q) / 4)                        // 480,000 (1875 full CTAs)
#define R_CONV_E  ((long long)N_EMP * 32)
#define R_CONV_C  ((long long)N_CON * 48)
#define R_XSPLIT  ((long long)N_LIC * 32)
#define R_BASE_CE (R_FILL)
#define R_BASE_CC (R_BASE_CE + R_CONV_E)
#define R_BASE_X  (R_BASE_CC + R_CONV_C)
#define R_BASE_T  (R_BASE_X + R_XSPLIT)
#define R_TAIL    (HDIM * 288)
#define K1_THREADS (R_BASE_T + R_TAIL)

__global__ void prep_all_kernel(const float* __restrict__ x_emp, const float* __restrict__ x_con,
                                const float* __restrict__ x_lic,
                                const float* __restrict__ Wl_p, const float* __restrict__ Wr_p,
                                const float* __restrict__ b_p,  const float* __restrict__ Wl_q,
                                const float* __restrict__ Wr_q, const float* __restrict__ b_q,
                                const void* eps, const void* epd,
                                const void* eqs, const void* eqd) {
    long long i = blockIdx.x * (long long)blockDim.x + threadIdx.x;
    if (blockIdx.x < (R_FILL / 256)) {
        __shared__ int s_is64;
        if (threadIdx.x < 32) {
            const unsigned int* probe = (const unsigned int*)eps;
            int lane = threadIdx.x;
            int ok = 1;
#pragma unroll
            for (int t = 0; t < 16; t++) ok &= (probe[1 + 2 * (lane + 32 * t)] == 0u);
            ok = __all_sync(0xffffffffu, ok);
            if (lane == 0) s_is64 = ok;
        }
        __syncthreads();
        const int is64 = s_is64;

        long long e = i * 4;
        int s[4], d[4];
        if (e < E_P) {
            if (is64) {
                longlong4 sv = ((const longlong4*)eps)[e >> 2];
                longlong4 dv = ((const longlong4*)epd)[e >> 2];
                s[0]=(int)sv.x; s[1]=(int)sv.y; s[2]=(int)sv.z; s[3]=(int)sv.w;
                d[0]=(int)dv.x; d[1]=(int)dv.y; d[2]=(int)dv.z; d[3]=(int)dv.w;
            } else {
                int4 sv = ((const int4*)eps)[e >> 2];
                int4 dv = ((const int4*)epd)[e >> 2];
                s[0]=sv.x; s[1]=sv.y; s[2]=sv.z; s[3]=sv.w;
                d[0]=dv.x; d[1]=dv.y; d[2]=dv.z; d[3]=dv.w;
            }
#pragma unroll
            for (int j = 0; j < 4; j++) {
                int pos = atomicAdd(&g_cnt_p[d[j]], 1);
                if (pos < CAP_P) g_col_p[(size_t)d[j] * CAP_P + pos] = s[j];
            }
        } else {
            long long k = e - E_P;
            if (is64) {
                longlong4 sv = ((const longlong4*)eqs)[k >> 2];
                longlong4 dv = ((const longlong4*)eqd)[k >> 2];
                s[0]=(int)sv.x; s[1]=(int)sv.y; s[2]=(int)sv.z; s[3]=(int)sv.w;
                d[0]=(int)dv.x; d[1]=(int)dv.y; d[2]=(int)dv.z; d[3]=(int)dv.w;
            } else {
                int4 sv = ((const int4*)eqs)[k >> 2];
                int4 dv = ((const int4*)eqd)[k >> 2];
                s[0]=sv.x; s[1]=sv.y; s[2]=sv.z; s[3]=sv.w;
                d[0]=dv.x; d[1]=dv.y; d[2]=dv.z; d[3]=dv.w;
            }
#pragma unroll
            for (int j = 0; j < 4; j++) {
                int pos = atomicAdd(&g_cnt_q[d[j]], 1);
                if (pos < CAP_Q) g_col_q[(size_t)d[j] * CAP_Q + pos] = s[j];
            }
        }
    } else if (i < R_BASE_CC) {
        long long j = i - R_BASE_CE;
        float4 v = *(const float4*)&x_emp[j * 4];
        *(uint2*)&g_xe[j * 2] = make_uint2(pack_h(v.x, v.y), pack_h(v.z, v.w));
    } else if (i < R_BASE_X) {
        long long j = i - R_BASE_CC;
        float4 v = *(const float4*)&x_con[j * 4];
        *(uint2*)&g_xc[j * 2] = make_uint2(pack_h(v.x, v.y), pack_h(v.z, v.w));
    } else if (i < R_BASE_T) {
        long long k = i - R_BASE_X;        // base is 32-aligned
        int row = (int)(k >> 5);
        int lane = (int)(k & 31);
        const float* xr = &x_lic[(size_t)row * D_LIC + lane * 8];
        float4 v0 = *(const float4*)&xr[0];
        float4 v1 = *(const float4*)&xr[4];
        uint4 h;
        h.x = pack_h(v0.x, v0.y);
        h.y = pack_h(v0.z, v0.w);
        h.z = pack_h(v1.x, v1.y);
        h.w = pack_h(v1.z, v1.w);
        *(uint4*)&g_Ax[(size_t)row * 128 + lane * 4] = h;
    } else {
        long long j = i - R_BASE_T;
        if (j < HDIM * 288) {
            int n  = (int)(j / 288);
            int kk = (int)(j % 288);
            float w[2];
#pragma unroll
            for (int t = 0; t < 2; t++) {
                int k = kk * 2 + t;
                if (k < D_EMP)              w[t] = 0.5f * Wl_p[k * HDIM + n];
                else if (k < D_EMP + D_CON) w[t] = 0.5f * Wl_q[(k - D_EMP) * HDIM + n];
                else {
                    int kr = k - (D_EMP + D_CON);
                    w[t] = 0.5f * (Wr_p[kr * HDIM + n] + Wr_q[kr * HDIM + n]);
                }
            }
            g_Wh[j] = pack_h(w[0], w[1]);
        }
        if (j < HDIM) g_b[j] = 0.5f * (b_p[j] + b_q[j]);
    }
}

// ---------------- K2: fused gather + fp16 tensor GEMM + bias + relu ------------
// Per CTA: 64 rows. Gather p/q directly into persistent smem A tile
// (64 rows x 656B, conflict-free for ldmatrix), then MMA over 18 chunks.
// Chunks 0-9 read A from persistent tile; chunks 10-17 double-buffer from g_Ax.
// smem: A 41984 | B 2x20480 | Ax 2x5120 = 93184 B; 2 CTAs/SM.
#define ASTR_B  656u
#define ASTR_U  164
#define SB_OFF  41984u
#define SAX_OFF (41984u + 40960u)
#define GEMM_SMEM 93184

__global__ __launch_bounds__(256, 2)
void gemm_fused_kernel(float* __restrict__ out) {
    extern __shared__ uint32_t sm[];
    const uint32_t smb = smem_u32(sm);

    const int tid    = threadIdx.x;
    const int lane   = tid & 31;
    const int wid    = tid >> 5;
    const int warp_m = wid & 1;
    const int warp_n = wid >> 1;
    const int m0     = blockIdx.x * 64;

    // ---- prefetch B chunk 0 (lands during gather) ----
    {
#pragma unroll
        for (int j = 0; j < 4; j++) {
            int idx = j * 256 + tid;
            int r = idx >> 2, q = idx & 3;
            cp16(smb + SB_OFF + r * 80 + q * 16, &g_Wh[(size_t)r * 288 + q * 4]);
        }
        asm volatile("cp.async.commit_group;" ::: "memory");
    }

    // ---- gather phase: warp wid handles rows [wid*8, wid*8+8) ----
#pragma unroll 1
    for (int t = 0; t < 8; t++) {
        const int lr = wid * 8 + t;           // local row
        const int r  = m0 + lr;               // global node
        // -- relation p -> u32 cols [0,64) --
        {
            const int deg = g_cnt_p[r];
            const int degc = min(deg, CAP_P);
            const size_t base = (size_t)r * CAP_P;
            float4 acc = make_float4(0.f, 0.f, 0.f, 0.f);
            int e = 0;
            for (; e + 3 < degc; e += 4) {
                int s0 = g_col_p[base + e],     s1 = g_col_p[base + e + 1];
                int s2 = g_col_p[base + e + 2], s3 = g_col_p[base + e + 3];
                uint2 u0 = *(const uint2*)&g_xe[(size_t)s0 * 64 + lane * 2];
                uint2 u1 = *(const uint2*)&g_xe[(size_t)s1 * 64 + lane * 2];
                uint2 u2 = *(const uint2*)&g_xe[(size_t)s2 * 64 + lane * 2];
                uint2 u3 = *(const uint2*)&g_xe[(size_t)s3 * 64 + lane * 2];
                float2 a0 = unpack_h(u0.x), b0 = unpack_h(u0.y);
                float2 a1 = unpack_h(u1.x), b1 = unpack_h(u1.y);
                float2 a2 = unpack_h(u2.x), b2 = unpack_h(u2.y);
                float2 a3 = unpack_h(u3.x), b3 = unpack_h(u3.y);
                acc.x += (a0.x + a1.x) + (a2.x + a3.x);
                acc.y += (a0.y + a1.y) + (a2.y + a3.y);
                acc.z += (b0.x + b1.x) + (b2.x + b3.x);
                acc.w += (b0.y + b1.y) + (b2.y + b3.y);
            }
            for (; e < degc; e++) {
                int s0 = g_col_p[base + e];
                uint2 u0 = *(const uint2*)&g_xe[(size_t)s0 * 64 + lane * 2];
                float2 a = unpack_h(u0.x), b = unpack_h(u0.y);
                acc.x += a.x; acc.y += a.y; acc.z += b.x; acc.w += b.y;
            }
            if (lane == 0) g_cnt_p[r] = 0;
            float inv = 1.0f / fmaxf((float)deg, 1.0f);
            *(uint2*)&sm[lr * ASTR_U + lane * 2] =
                make_uint2(pack_h(acc.x * inv, acc.y * inv),
                           pack_h(acc.z * inv, acc.w * inv));
        }
        // -- relation q -> u32 cols [64,160) --
        {
            const int deg = g_cnt_q[r];
            const int degc = min(deg, CAP_Q);
            const size_t base = (size_t)r * CAP_Q;
            float4 a4 = make_float4(0.f, 0.f, 0.f, 0.f);
            float2 a2 = make_float2(0.f, 0.f);
            int e = 0;
            for (; e + 3 < degc; e += 4) {
                int s0 = g_col_q[base + e],     s1 = g_col_q[base + e + 1];
                int s2 = g_col_q[base + e + 2], s3 = g_col_q[base + e + 3];
                const uint32_t* r0 = &g_xc[(size_t)s0 * 96];
                const uint32_t* r1 = &g_xc[(size_t)s1 * 96];
                const uint32_t* r2 = &g_xc[(size_t)s2 * 96];
                const uint32_t* r3 = &g_xc[(size_t)s3 * 96];
                uint2 u0 = *(const uint2*)&r0[lane * 2];
                uint2 u1 = *(const uint2*)&r1[lane * 2];
                uint2 u2 = *(const uint2*)&r2[lane * 2];
                uint2 u3 = *(const uint2*)&r3[lane * 2];
                uint32_t w0 = r0[64 + lane], w1 = r1[64 + lane];
                uint32_t w2 = r2[64 + lane], w3 = r3[64 + lane];
                float2 p0 = unpack_h(u0.x), q0 = unpack_h(u0.y);
                float2 p1 = unpack_h(u1.x), q1 = unpack_h(u1.y);
                float2 p2 = unpack_h(u2.x), q2 = unpack_h(u2.y);
                float2 p3 = unpack_h(u3.x), q3 = unpack_h(u3.y);
                float2 g0 = unpack_h(w0), g1 = unpack_h(w1);
                float2 g2 = unpack_h(w2), g3 = unpack_h(w3);
                a4.x += (p0.x + p1.x) + (p2.x + p3.x);
                a4.y += (p0.y + p1.y) + (p2.y + p3.y);
                a4.z += (q0.x + q1.x) + (q2.x + q3.x);
                a4.w += (q0.y + q1.y) + (q2.y + q3.y);
                a2.x += (g0.x + g1.x) + (g2.x + g3.x);
                a2.y += (g0.y + g1.y) + (g2.y + g3.y);
            }
            for (; e < degc; e++) {
                int s0 = g_col_q[base + e];
                const uint32_t* r0 = &g_xc[(size_t)s0 * 96];
                uint2 u0 = *(const uint2*)&r0[lane * 2];
                uint32_t w0 = r0[64 + lane];
                float2 a = unpack_h(u0.x), b = unpack_h(u0.y);
                float2 g = unpack_h(w0);
                a4.x += a.x; a4.y += a.y; a4.z += b.x; a4.w += b.y;
                a2.x += g.x; a2.y += g.y;
            }
            if (lane == 0) g_cnt_q[r] = 0;
            float inv = 1.0f / fmaxf((float)deg, 1.0f);
            *(uint2*)&sm[lr * ASTR_U + 64 + lane * 2] =
                make_uint2(pack_h(a4.x * inv, a4.y * inv),
                           pack_h(a4.z * inv, a4.w * inv));
            sm[lr * ASTR_U + 128 + lane] = pack_h(a2.x * inv, a2.y * inv);
        }
    }
    __syncthreads();   // persistent A tile ready

    // ---- MMA pipeline ----
    const int lrow8 = (lane & 7) + ((lane >> 3) & 1) * 8;
    const int lk    = ((lane >> 4) & 1) * 16;
    const uint32_t aoffP = (uint32_t)(warp_m * 32 + lrow8) * ASTR_B + lk;
    const uint32_t aoffX = (uint32_t)(warp_m * 32 + lrow8) * 80 + lk;
    const uint32_t boff  = SB_OFF + (uint32_t)(warp_n * 64 + lrow8) * 80 + lk;
    const int ar = tid >> 2, aq = tid & 3;

    float acc[2][8][4];
#pragma unroll
    for (int i = 0; i < 2; i++)
#pragma unroll
        for (int j = 0; j < 8; j++)
#pragma unroll
            for (int l = 0; l < 4; l++) acc[i][j][l] = 0.f;

    for (int c = 0; c < NCHUNK; c++) {
        asm volatile("cp.async.wait_group 0;" ::: "memory");
        __syncthreads();

        if (c < NCHUNK - 1) {
            const int nx = c + 1;
            uint32_t sbB = smb + SB_OFF + (nx & 1) * 20480;
#pragma unroll
            for (int j = 0; j < 4; j++) {
                int idx = j * 256 + tid;
                int r = idx >> 2, q = idx & 3;
                cp16(sbB + r * 80 + q * 16, &g_Wh[(size_t)r * 288 + nx * 16 + q * 4]);
            }
            if (nx >= 10) {
                cp16(smb + SAX_OFF + (nx & 1) * 5120 + ar * 80 + aq * 16,
                     &g_Ax[(size_t)(m0 + ar) * 128 + (nx - 10) * 16 + aq * 4]);
            }
            asm volatile("cp.async.commit_group;" ::: "memory");
        }

        uint32_t a0, a1;
        if (c < 10) {
            a0 = smb + aoffP + c * 64;
            a1 = a0 + 16 * ASTR_B;
        } else {
            a0 = smb + SAX_OFF + (c & 1) * 5120 + aoffX;
            a1 = a0 + 16 * 80;
        }
        const uint32_t b0a = smb + boff + (c & 1) * 20480 - SB_OFF + SB_OFF; // = stage base + boff rel
        const uint32_t bbase = smb + SB_OFF + (c & 1) * 20480 +
                               (uint32_t)(warp_n * 64 + lrow8) * 80 + lk;
        (void)b0a;
#pragma unroll
        for (int ks = 0; ks < 2; ks++) {
            uint32_t ah[2][4], bb[4][4];
            ldsm4(a0 + ks * 32, ah[0]);
            ldsm4(a1 + ks * 32, ah[1]);
#pragma unroll
            for (int g = 0; g < 4; g++)
                ldsm4(bbase + g * 1280 + ks * 32, bb[g]);
#pragma unroll
            for (int j = 0; j < 8; j++) {
                uint32_t b0 = bb[j >> 1][j & 1];
                uint32_t b1 = bb[j >> 1][(j & 1) + 2];
                mma_f16(acc[0][j], ah[0], b0, b1);
                mma_f16(acc[1][j], ah[1], b0, b1);
            }
        }
    }

    // ---- epilogue: bias + relu ----
#pragma unroll
    for (int j = 0; j < 8; j++) {
        int col = warp_n * 64 + j * 8 + (lane & 3) * 2;
        float b0 = g_b[col], b1 = g_b[col + 1];
#pragma unroll
        for (int mf = 0; mf < 2; mf++) {
            int row = m0 + warp_m * 32 + mf * 16 + (lane >> 2);
            float2 o0, o1;
            o0.x = fmaxf(acc[mf][j][0] + b0, 0.f);
            o0.y = fmaxf(acc[mf][j][1] + b1, 0.f);
            o1.x = fmaxf(acc[mf][j][2] + b0, 0.f);
            o1.y = fmaxf(acc[mf][j][3] + b1, 0.f);
            *(float2*)&out[(size_t)row * HDIM + col] = o0;
            *(float2*)&out[(size_t)(row + 8) * HDIM + col] = o1;
        }
    }
}

// ---------------- launch (sequential, 2 kernels) -------------------------------
extern "C" void kernel_launch(void* const* d_in, const int* in_sizes, int n_in,
                              void* d_out, int out_size) {
    const float* x_lic = (const float*)d_in[0];
    const float* x_emp = (const float*)d_in[1];
    const float* x_con = (const float*)d_in[2];
    const float* Wl_p  = (const float*)d_in[3];
    const float* Wr_p  = (const float*)d_in[4];
    const float* b_p   = (const float*)d_in[5];
    const float* Wl_q  = (const float*)d_in[6];
    const float* Wr_q  = (const float*)d_in[7];
    const float* b_q   = (const float*)d_in[8];
    const void*  eps   = d_in[9];
    const void*  epd   = d_in[10];
    const void*  eqs   = d_in[11];
    const void*  eqd   = d_in[12];
    float* out = (float*)d_out;

    cudaFuncSetAttribute(gemm_fused_kernel,
                         cudaFuncAttributeMaxDynamicSharedMemorySize, GEMM_SMEM);

    prep_all_kernel<<<(int)((K1_THREADS + 255) / 256), 256>>>(
        x_emp, x_con, x_lic, Wl_p, Wr_p, b_p, Wl_q, Wr_q, b_q,
        eps, epd, eqs, eqd);
    gemm_fused_kernel<<<N_LIC / 64, 256, GEMM_SMEM>>>(out);
}

// round 13
// speedup vs baseline: 1.6532x; 1.6532x over previous
#include <cuda_runtime.h>
#include <cuda_fp16.h>
#include <cstdint>

#define N_LIC 40000
#define N_EMP 80000
#define N_CON 60000
#define D_LIC 256
#define D_EMP 128
#define D_CON 192
#define HDIM  256
#define E_P   1280000
#define E_Q   640000
#define KTOT  576    // 128 + 192 + 256
#define KH    288    // KTOT/2 packed u32 per row
#define NCH9  9      // k-chunks of 64 halves (32 u32)

#define CAP_P 96     // max degree, relation p (mean 32)
#define CAP_Q 64     // max degree, relation q (mean 16)

// ---------------- scratch (static device globals; no runtime alloc) --------
__device__ uint32_t g_Ah[(size_t)N_LIC * KH];      // A packed fp16x2 (46MB)
__device__ uint32_t g_Wh[(size_t)HDIM * KH];       // W^T packed fp16x2
__device__ uint32_t g_xe[(size_t)N_EMP * 64];      // x_emp fp16 packed (20MB)
__device__ uint32_t g_xc[(size_t)N_CON * 96];      // x_con fp16 packed (23MB)
__device__ float    g_b[HDIM];
__device__ int      g_cnt_p[N_LIC];                // zero-init; self-cleaned by gather
__device__ int      g_cnt_q[N_LIC];
__device__ int      g_col_p[(size_t)N_LIC * CAP_P];
__device__ int      g_col_q[(size_t)N_LIC * CAP_Q];

// ---------------- helpers ------------------------------------------------------
__device__ __forceinline__ uint32_t pack_h(float x, float y) {
    __half2 h = __floats2half2_rn(x, y);
    return *(uint32_t*)&h;
}
__device__ __forceinline__ float2 unpack_h(uint32_t u) {
    return __half22float2(*(__half2*)&u);
}
__device__ __forceinline__ uint32_t smem_u32(const void* p) {
    uint32_t a;
    asm("{ .reg .u64 t; cvta.to.shared.u64 t, %1; cvt.u32.u64 %0, t; }" : "=r"(a) : "l"(p));
    return a;
}
__device__ __forceinline__ void cp16(uint32_t dst, const void* src) {
    asm volatile("cp.async.cg.shared.global [%0], [%1], 16;" :: "r"(dst), "l"(src));
}
__device__ __forceinline__ void ldsm4(uint32_t addr, uint32_t* r) {
    asm volatile("ldmatrix.sync.aligned.m8n8.x4.shared.b16 {%0,%1,%2,%3}, [%4];"
                 : "=r"(r[0]), "=r"(r[1]), "=r"(r[2]), "=r"(r[3]) : "r"(addr));
}
__device__ __forceinline__ void mma_f16(float* c, const uint32_t* a, uint32_t b0, uint32_t b1) {
    asm volatile(
        "mma.sync.aligned.m16n8k16.row.col.f32.f16.f16.f32 "
        "{%0,%1,%2,%3}, {%4,%5,%6,%7}, {%8,%9}, {%0,%1,%2,%3};"
        : "+f"(c[0]), "+f"(c[1]), "+f"(c[2]), "+f"(c[3])
        : "r"(a[0]), "r"(a[1]), "r"(a[2]), "r"(a[3]), "r"(b0), "r"(b1));
}

// ---------------- K1: fused fill + conv + xsplit + weight-prep ------------------
#define R_FILL    ((E_P + E_Q) / 4)                        // 480,000 (1875 full CTAs)
#define R_CONV_E  ((long long)N_EMP * 32)
#define R_CONV_C  ((long long)N_CON * 48)
#define R_XSPLIT  ((long long)N_LIC * 32)
#define R_BASE_CE (R_FILL)
#define R_BASE_CC (R_BASE_CE + R_CONV_E)
#define R_BASE_X  (R_BASE_CC + R_CONV_C)
#define R_BASE_T  (R_BASE_X + R_XSPLIT)
#define R_TAIL    (HDIM * KH)
#define K1_THREADS (R_BASE_T + R_TAIL)

__global__ void prep_all_kernel(const float* __restrict__ x_emp, const float* __restrict__ x_con,
                                const float* __restrict__ x_lic,
                                const float* __restrict__ Wl_p, const float* __restrict__ Wr_p,
                                const float* __restrict__ b_p,  const float* __restrict__ Wl_q,
                                const float* __restrict__ Wr_q, const float* __restrict__ b_q,
                                const void* eps, const void* epd,
                                const void* eqs, const void* eqd) {
    long long i = blockIdx.x * (long long)blockDim.x + threadIdx.x;
    if (blockIdx.x < (R_FILL / 256)) {
        __shared__ int s_is64;
        if (threadIdx.x < 32) {
            const unsigned int* probe = (const unsigned int*)eps;
            int lane = threadIdx.x;
            int ok = 1;
#pragma unroll
            for (int t = 0; t < 16; t++) ok &= (probe[1 + 2 * (lane + 32 * t)] == 0u);
            ok = __all_sync(0xffffffffu, ok);
            if (lane == 0) s_is64 = ok;
        }
        __syncthreads();
        const int is64 = s_is64;

        long long e = i * 4;
        int s[4], d[4];
        if (e < E_P) {
            if (is64) {
                longlong4 sv = ((const longlong4*)eps)[e >> 2];
                longlong4 dv = ((const longlong4*)epd)[e >> 2];
                s[0]=(int)sv.x; s[1]=(int)sv.y; s[2]=(int)sv.z; s[3]=(int)sv.w;
                d[0]=(int)dv.x; d[1]=(int)dv.y; d[2]=(int)dv.z; d[3]=(int)dv.w;
            } else {
                int4 sv = ((const int4*)eps)[e >> 2];
                int4 dv = ((const int4*)epd)[e >> 2];
                s[0]=sv.x; s[1]=sv.y; s[2]=sv.z; s[3]=sv.w;
                d[0]=dv.x; d[1]=dv.y; d[2]=dv.z; d[3]=dv.w;
            }
#pragma unroll
            for (int j = 0; j < 4; j++) {
                int pos = atomicAdd(&g_cnt_p[d[j]], 1);
                if (pos < CAP_P) g_col_p[(size_t)d[j] * CAP_P + pos] = s[j];
            }
        } else {
            long long k = e - E_P;
            if (is64) {
                longlong4 sv = ((const longlong4*)eqs)[k >> 2];
                longlong4 dv = ((const longlong4*)eqd)[k >> 2];
                s[0]=(int)sv.x; s[1]=(int)sv.y; s[2]=(int)sv.z; s[3]=(int)sv.w;
                d[0]=(int)dv.x; d[1]=(int)dv.y; d[2]=(int)dv.z; d[3]=(int)dv.w;
            } else {
                int4 sv = ((const int4*)eqs)[k >> 2];
                int4 dv = ((const int4*)eqd)[k >> 2];
                s[0]=sv.x; s[1]=sv.y; s[2]=sv.z; s[3]=sv.w;
                d[0]=dv.x; d[1]=dv.y; d[2]=dv.z; d[3]=dv.w;
            }
#pragma unroll
            for (int j = 0; j < 4; j++) {
                int pos = atomicAdd(&g_cnt_q[d[j]], 1);
                if (pos < CAP_Q) g_col_q[(size_t)d[j] * CAP_Q + pos] = s[j];
            }
        }
    } else if (i < R_BASE_CC) {
        long long j = i - R_BASE_CE;
        float4 v = *(const float4*)&x_emp[j * 4];
        *(uint2*)&g_xe[j * 2] = make_uint2(pack_h(v.x, v.y), pack_h(v.z, v.w));
    } else if (i < R_BASE_X) {
        long long j = i - R_BASE_CC;
        float4 v = *(const float4*)&x_con[j * 4];
        *(uint2*)&g_xc[j * 2] = make_uint2(pack_h(v.x, v.y), pack_h(v.z, v.w));
    } else if (i < R_BASE_T) {
        long long k = i - R_BASE_X;        // base is 32-aligned
        int row = (int)(k >> 5);
        int lane = (int)(k & 31);
        const float* xr = &x_lic[(size_t)row * D_LIC + lane * 8];
        float4 v0 = *(const float4*)&xr[0];
        float4 v1 = *(const float4*)&xr[4];
        uint4 h;
        h.x = pack_h(v0.x, v0.y);
        h.y = pack_h(v0.z, v0.w);
        h.z = pack_h(v1.x, v1.y);
        h.w = pack_h(v1.z, v1.w);
        *(uint4*)&g_Ah[(size_t)row * KH + 160 + lane * 4] = h;
    } else {
        long long j = i - R_BASE_T;
        if (j < HDIM * KH) {
            int n  = (int)(j / KH);
            int kk = (int)(j % KH);
            float w[2];
#pragma unroll
            for (int t = 0; t < 2; t++) {
                int k = kk * 2 + t;
                if (k < D_EMP)              w[t] = 0.5f * Wl_p[k * HDIM + n];
                else if (k < D_EMP + D_CON) w[t] = 0.5f * Wl_q[(k - D_EMP) * HDIM + n];
                else {
                    int kr = k - (D_EMP + D_CON);
                    w[t] = 0.5f * (Wr_p[kr * HDIM + n] + Wr_q[kr * HDIM + n]);
                }
            }
            g_Wh[j] = pack_h(w[0], w[1]);
        }
        if (j < HDIM) g_b[j] = 0.5f * (b_p[j] + b_q[j]);
    }
}

// ---------------- K2: gather + normalize + pack A; self-cleans counters --------
__global__ void gather_kernel() {
    const int gw = (int)((blockIdx.x * (long long)blockDim.x + threadIdx.x) >> 5);
    const int lane = threadIdx.x & 31;
    if (gw < N_LIC) {
        const int d = gw;
        const int deg = g_cnt_p[d];
        const int degc = min(deg, CAP_P);
        const size_t base = (size_t)d * CAP_P;
        float4 acc = make_float4(0.f, 0.f, 0.f, 0.f);
        int e = 0;
        for (; e + 3 < degc; e += 4) {
            int s0 = g_col_p[base + e],     s1 = g_col_p[base + e + 1];
            int s2 = g_col_p[base + e + 2], s3 = g_col_p[base + e + 3];
            uint2 u0 = *(const uint2*)&g_xe[(size_t)s0 * 64 + lane * 2];
            uint2 u1 = *(const uint2*)&g_xe[(size_t)s1 * 64 + lane * 2];
            uint2 u2 = *(const uint2*)&g_xe[(size_t)s2 * 64 + lane * 2];
            uint2 u3 = *(const uint2*)&g_xe[(size_t)s3 * 64 + lane * 2];
            float2 a0 = unpack_h(u0.x), b0 = unpack_h(u0.y);
            float2 a1 = unpack_h(u1.x), b1 = unpack_h(u1.y);
            float2 a2 = unpack_h(u2.x), b2 = unpack_h(u2.y);
            float2 a3 = unpack_h(u3.x), b3 = unpack_h(u3.y);
            acc.x += (a0.x + a1.x) + (a2.x + a3.x);
            acc.y += (a0.y + a1.y) + (a2.y + a3.y);
            acc.z += (b0.x + b1.x) + (b2.x + b3.x);
            acc.w += (b0.y + b1.y) + (b2.y + b3.y);
        }
        for (; e < degc; e++) {
            int s0 = g_col_p[base + e];
            uint2 u0 = *(const uint2*)&g_xe[(size_t)s0 * 64 + lane * 2];
            float2 a = unpack_h(u0.x), b = unpack_h(u0.y);
            acc.x += a.x; acc.y += a.y; acc.z += b.x; acc.w += b.y;
        }
        if (lane == 0) g_cnt_p[d] = 0;
        float inv = 1.0f / fmaxf((float)deg, 1.0f);
        size_t o = (size_t)d * KH + lane * 2;
        *(uint2*)&g_Ah[o] = make_uint2(pack_h(acc.x * inv, acc.y * inv),
                                       pack_h(acc.z * inv, acc.w * inv));
    } else if (gw < 2 * N_LIC) {
        const int d = gw - N_LIC;
        const int deg = g_cnt_q[d];
        const int degc = min(deg, CAP_Q);
        const size_t base = (size_t)d * CAP_Q;
        float4 a4 = make_float4(0.f, 0.f, 0.f, 0.f);
        float2 a2 = make_float2(0.f, 0.f);
        int e = 0;
        for (; e + 3 < degc; e += 4) {
            int s0 = g_col_q[base + e],     s1 = g_col_q[base + e + 1];
            int s2 = g_col_q[base + e + 2], s3 = g_col_q[base + e + 3];
            const uint32_t* r0 = &g_xc[(size_t)s0 * 96];
            const uint32_t* r1 = &g_xc[(size_t)s1 * 96];
            const uint32_t* r2 = &g_xc[(size_t)s2 * 96];
            const uint32_t* r3 = &g_xc[(size_t)s3 * 96];
            uint2 u0 = *(const uint2*)&r0[lane * 2];
            uint2 u1 = *(const uint2*)&r1[lane * 2];
            uint2 u2 = *(const uint2*)&r2[lane * 2];
            uint2 u3 = *(const uint2*)&r3[lane * 2];
            uint32_t w0 = r0[64 + lane], w1 = r1[64 + lane];
            uint32_t w2 = r2[64 + lane], w3 = r3[64 + lane];
            float2 p0 = unpack_h(u0.x), q0 = unpack_h(u0.y);
            float2 p1 = unpack_h(u1.x), q1 = unpack_h(u1.y);
            float2 p2 = unpack_h(u2.x), q2 = unpack_h(u2.y);
            float2 p3 = unpack_h(u3.x), q3 = unpack_h(u3.y);
            float2 g0 = unpack_h(w0), g1 = unpack_h(w1);
            float2 g2 = unpack_h(w2), g3 = unpack_h(w3);
            a4.x += (p0.x + p1.x) + (p2.x + p3.x);
            a4.y += (p0.y + p1.y) + (p2.y + p3.y);
            a4.z += (q0.x + q1.x) + (q2.x + q3.x);
            a4.w += (q0.y + q1.y) + (q2.y + q3.y);
            a2.x += (g0.x + g1.x) + (g2.x + g3.x);
            a2.y += (g0.y + g1.y) + (g2.y + g3.y);
        }
        for (; e < degc; e++) {
            int s0 = g_col_q[base + e];
            const uint32_t* r0 = &g_xc[(size_t)s0 * 96];
            uint2 u0 = *(const uint2*)&r0[lane * 2];
            uint32_t w0 = r0[64 + lane];
            float2 a = unpack_h(u0.x), b = unpack_h(u0.y);
            float2 g = unpack_h(w0);
            a4.x += a.x; a4.y += a.y; a4.z += b.x; a4.w += b.y;
            a2.x += g.x; a2.y += g.y;
        }
        if (lane == 0) g_cnt_q[d] = 0;
        float inv = 1.0f / fmaxf((float)deg, 1.0f);
        size_t o = (size_t)d * KH + 64 + lane * 2;
        *(uint2*)&g_Ah[o] = make_uint2(pack_h(a4.x * inv, a4.y * inv),
                                       pack_h(a4.z * inv, a4.w * inv));
        g_Ah[(size_t)d * KH + 128 + lane] = pack_h(a2.x * inv, a2.y * inv);
    }
}

// ---------------- K3: fp16 tensor GEMM + bias + relu (64x256 tile, BK=64) -----
// Stage: A 64x144B (9216) + B 256x144B (36864) = 46080; 2 stages (dyn smem).
// 8 warps: 2m x 4n, warp tile 32x64.  Row stride 144B -> ldmatrix conflict-free.
#define ASTR 144u
#define BOFF 9216u
#define STG  46080u
#define GEMM_SMEM (2 * 46080)

__global__ __launch_bounds__(256, 2)
void gemm_mma_kernel(float* __restrict__ out) {
    extern __shared__ uint32_t sm[];
    const uint32_t smb = smem_u32(sm);

    const int tid    = threadIdx.x;
    const int lane   = tid & 31;
    const int wid    = tid >> 5;
    const int warp_m = wid & 1;
    const int warp_n = wid >> 1;          // 0..3 -> 64-col slab
    const int m0     = blockIdx.x * 64;

    const int lrow8 = (lane & 7) + ((lane >> 3) & 1) * 8;
    const int lk    = ((lane >> 4) & 1) * 16;
    const uint32_t aoff = (uint32_t)(warp_m * 32 + lrow8) * ASTR + lk;
    const uint32_t boff = BOFF + (uint32_t)(warp_n * 64 + lrow8) * ASTR + lk;

    const int ar = tid >> 2, aq = tid & 3;

    float acc[2][8][4];
#pragma unroll
    for (int i = 0; i < 2; i++)
#pragma unroll
        for (int j = 0; j < 8; j++)
#pragma unroll
            for (int l = 0; l < 4; l++) acc[i][j][l] = 0.f;

    // prefetch chunk 0
    {
        size_t abase = (size_t)(m0 + ar) * KH;
        cp16(smb + ar * ASTR + aq * 16,       &g_Ah[abase + aq * 4]);
        cp16(smb + ar * ASTR + (aq + 4) * 16, &g_Ah[abase + (aq + 4) * 4]);
#pragma unroll
        for (int j = 0; j < 8; j++) {
            int idx = j * 256 + tid;
            int r = idx >> 3, p = idx & 7;
            cp16(smb + BOFF + r * ASTR + p * 16, &g_Wh[(size_t)r * KH + p * 4]);
        }
        asm volatile("cp.async.commit_group;" ::: "memory");
    }

    for (int c = 0; c < NCH9; c++) {
        asm volatile("cp.async.wait_group 0;" ::: "memory");
        __syncthreads();

        if (c < NCH9 - 1) {
            const int nx = c + 1;
            uint32_t sb = smb + (nx & 1) * STG;
            size_t abase = (size_t)(m0 + ar) * KH + nx * 32;
            cp16(sb + ar * ASTR + aq * 16,       &g_Ah[abase + aq * 4]);
            cp16(sb + ar * ASTR + (aq + 4) * 16, &g_Ah[abase + (aq + 4) * 4]);
#pragma unroll
            for (int j = 0; j < 8; j++) {
                int idx = j * 256 + tid;
                int r = idx >> 3, p = idx & 7;
                cp16(sb + BOFF + r * ASTR + p * 16,
                     &g_Wh[(size_t)r * KH + nx * 32 + p * 4]);
            }
            asm volatile("cp.async.commit_group;" ::: "memory");
        }

        const uint32_t s0 = smb + (c & 1) * STG;
#pragma unroll
        for (int ks = 0; ks < 4; ks++) {
            uint32_t ah[2][4], bb[4][4];
            ldsm4(s0 + aoff + ks * 32,              ah[0]);
            ldsm4(s0 + aoff + 16 * ASTR + ks * 32,  ah[1]);
#pragma unroll
            for (int g = 0; g < 4; g++)
                ldsm4(s0 + boff + g * (16 * ASTR) + ks * 32, bb[g]);
#pragma unroll
            for (int j = 0; j < 8; j++) {
                uint32_t b0 = bb[j >> 1][j & 1];
                uint32_t b1 = bb[j >> 1][(j & 1) + 2];
                mma_f16(acc[0][j], ah[0], b0, b1);
                mma_f16(acc[1][j], ah[1], b0, b1);
            }
        }
    }

    // epilogue: bias + relu
#pragma unroll
    for (int j = 0; j < 8; j++) {
        int col = warp_n * 64 + j * 8 + (lane & 3) * 2;
        float b0 = g_b[col], b1 = g_b[col + 1];
#pragma unroll
        for (int mf = 0; mf < 2; mf++) {
            int row = m0 + warp_m * 32 + mf * 16 + (lane >> 2);
            float2 o0, o1;
            o0.x = fmaxf(acc[mf][j][0] + b0, 0.f);
            o0.y = fmaxf(acc[mf][j][1] + b1, 0.f);
            o1.x = fmaxf(acc[mf][j][2] + b0, 0.f);
            o1.y = fmaxf(acc[mf][j][3] + b1, 0.f);
            *(float2*)&out[(size_t)row * HDIM + col] = o0;
            *(float2*)&out[(size_t)(row + 8) * HDIM + col] = o1;
        }
    }
}

// ---------------- launch (sequential, 3 kernels) -------------------------------
extern "C" void kernel_launch(void* const* d_in, const int* in_sizes, int n_in,
                              void* d_out, int out_size) {
    const float* x_lic = (const float*)d_in[0];
    const float* x_emp = (const float*)d_in[1];
    const float* x_con = (const float*)d_in[2];
    const float* Wl_p  = (const float*)d_in[3];
    const float* Wr_p  = (const float*)d_in[4];
    const float* b_p   = (const float*)d_in[5];
    const float* Wl_q  = (const float*)d_in[6];
    const float* Wr_q  = (const float*)d_in[7];
    const float* b_q   = (const float*)d_in[8];
    const void*  eps   = d_in[9];
    const void*  epd   = d_in[10];
    const void*  eqs   = d_in[11];
    const void*  eqd   = d_in[12];
    float* out = (float*)d_out;

    cudaFuncSetAttribute(gemm_mma_kernel,
                         cudaFuncAttributeMaxDynamicSharedMemorySize, GEMM_SMEM);

    prep_all_kernel<<<(int)((K1_THREADS + 255) / 256), 256>>>(
        x_emp, x_con, x_lic, Wl_p, Wr_p, b_p, Wl_q, Wr_q, b_q,
        eps, epd, eqs, eqd);
    gather_kernel<<<(2 * N_LIC * 32) / 256, 256>>>();
    gemm_mma_kernel<<<N_LIC / 64, 256, GEMM_SMEM>>>(out);
}

// round 14
// speedup vs baseline: 1.6790x; 1.0156x over previous
#include <cuda_runtime.h>
#include <cuda_fp16.h>
#include <cstdint>

#define N_LIC 40000
#define N_EMP 80000
#define N_CON 60000
#define D_LIC 256
#define D_EMP 128
#define D_CON 192
#define HDIM  256
#define E_P   1280000
#define E_Q   640000
#define KTOT  576    // 128 + 192 + 256
#define KH    288    // KTOT/2 packed u32 per row
#define NCH9  9      // k-chunks of 64 halves (32 u32)

#define CAP_P 96     // max degree, relation p (mean 32)
#define CAP_Q 64     // max degree, relation q (mean 16)

// ---------------- scratch (static device globals; no runtime alloc) --------
__device__ uint32_t g_Ah[(size_t)N_LIC * KH];      // A packed fp16x2 (46MB)
__device__ uint32_t g_Wh[(size_t)HDIM * KH];       // W^T packed fp16x2
__device__ uint32_t g_xe[(size_t)N_EMP * 64];      // x_emp fp16 packed (20MB)
__device__ uint32_t g_xc[(size_t)N_CON * 96];      // x_con fp16 packed (23MB)
__device__ float    g_b[HDIM];
__device__ int      g_cnt_p[N_LIC];                // zero-init; self-cleaned by gather
__device__ int      g_cnt_q[N_LIC];
__device__ int      g_col_p[(size_t)N_LIC * CAP_P];
__device__ int      g_col_q[(size_t)N_LIC * CAP_Q];

// ---------------- helpers ------------------------------------------------------
__device__ __forceinline__ uint32_t pack_h(float x, float y) {
    __half2 h = __floats2half2_rn(x, y);
    return *(uint32_t*)&h;
}
__device__ __forceinline__ float2 unpack_h(uint32_t u) {
    return __half22float2(*(__half2*)&u);
}
__device__ __forceinline__ uint32_t smem_u32(const void* p) {
    uint32_t a;
    asm("{ .reg .u64 t; cvta.to.shared.u64 t, %1; cvt.u32.u64 %0, t; }" : "=r"(a) : "l"(p));
    return a;
}
__device__ __forceinline__ void cp16(uint32_t dst, const void* src) {
    asm volatile("cp.async.cg.shared.global [%0], [%1], 16;" :: "r"(dst), "l"(src));
}
__device__ __forceinline__ void ldsm4(uint32_t addr, uint32_t* r) {
    asm volatile("ldmatrix.sync.aligned.m8n8.x4.shared.b16 {%0,%1,%2,%3}, [%4];"
                 : "=r"(r[0]), "=r"(r[1]), "=r"(r[2]), "=r"(r[3]) : "r"(addr));
}
__device__ __forceinline__ void mma_f16(float* c, const uint32_t* a, uint32_t b0, uint32_t b1) {
    asm volatile(
        "mma.sync.aligned.m16n8k16.row.col.f32.f16.f16.f32 "
        "{%0,%1,%2,%3}, {%4,%5,%6,%7}, {%8,%9}, {%0,%1,%2,%3};"
        : "+f"(c[0]), "+f"(c[1]), "+f"(c[2]), "+f"(c[3])
        : "r"(a[0]), "r"(a[1]), "r"(a[2]), "r"(a[3]), "r"(b0), "r"(b1));
}

// ---------------- K1: fused fill + conv + xsplit + weight-prep ------------------
// MLP-4 ranges: each conv/xsplit thread handles 4 independent 16B granules.
#define R_FILL    480000LL                          // (E_P+E_Q)/4, 1875 full CTAs
#define T_CONV_E  640000LL                          // N_EMP*32/4 granule-quads
#define T_CONV_C  720000LL                          // N_CON*48/4
#define T_XSPLIT  640000LL                          // N_LIC*64/4
#define R_BASE_CE (R_FILL)
#define R_BASE_CC (R_BASE_CE + T_CONV_E)
#define R_BASE_X  (R_BASE_CC + T_CONV_C)
#define R_BASE_T  (R_BASE_X + T_XSPLIT)
#define R_TAIL    ((long long)(HDIM * KH))
#define K1_THREADS (R_BASE_T + R_TAIL)

__global__ void prep_all_kernel(const float* __restrict__ x_emp, const float* __restrict__ x_con,
                                const float* __restrict__ x_lic,
                                const float* __restrict__ Wl_p, const float* __restrict__ Wr_p,
                                const float* __restrict__ b_p,  const float* __restrict__ Wl_q,
                                const float* __restrict__ Wr_q, const float* __restrict__ b_q,
                                const void* eps, const void* epd,
                                const void* eqs, const void* eqd) {
    long long i = blockIdx.x * (long long)blockDim.x + threadIdx.x;
    if (blockIdx.x < (int)(R_FILL / 256)) {
        __shared__ int s_is64;
        if (threadIdx.x < 32) {
            const unsigned int* probe = (const unsigned int*)eps;
            int lane = threadIdx.x;
            int ok = 1;
#pragma unroll
            for (int t = 0; t < 16; t++) ok &= (probe[1 + 2 * (lane + 32 * t)] == 0u);
            ok = __all_sync(0xffffffffu, ok);
            if (lane == 0) s_is64 = ok;
        }
        __syncthreads();
        const int is64 = s_is64;

        long long e = i * 4;
        int s[4], d[4];
        if (e < E_P) {
            if (is64) {
                longlong4 sv = ((const longlong4*)eps)[e >> 2];
                longlong4 dv = ((const longlong4*)epd)[e >> 2];
                s[0]=(int)sv.x; s[1]=(int)sv.y; s[2]=(int)sv.z; s[3]=(int)sv.w;
                d[0]=(int)dv.x; d[1]=(int)dv.y; d[2]=(int)dv.z; d[3]=(int)dv.w;
            } else {
                int4 sv = ((const int4*)eps)[e >> 2];
                int4 dv = ((const int4*)epd)[e >> 2];
                s[0]=sv.x; s[1]=sv.y; s[2]=sv.z; s[3]=sv.w;
                d[0]=dv.x; d[1]=dv.y; d[2]=dv.z; d[3]=dv.w;
            }
#pragma unroll
            for (int j = 0; j < 4; j++) {
                int pos = atomicAdd(&g_cnt_p[d[j]], 1);
                if (pos < CAP_P) g_col_p[(size_t)d[j] * CAP_P + pos] = s[j];
            }
        } else {
            long long k = e - E_P;
            if (is64) {
                longlong4 sv = ((const longlong4*)eqs)[k >> 2];
                longlong4 dv = ((const longlong4*)eqd)[k >> 2];
                s[0]=(int)sv.x; s[1]=(int)sv.y; s[2]=(int)sv.z; s[3]=(int)sv.w;
                d[0]=(int)dv.x; d[1]=(int)dv.y; d[2]=(int)dv.z; d[3]=(int)dv.w;
            } else {
                int4 sv = ((const int4*)eqs)[k >> 2];
                int4 dv = ((const int4*)eqd)[k >> 2];
                s[0]=sv.x; s[1]=sv.y; s[2]=sv.z; s[3]=sv.w;
                d[0]=dv.x; d[1]=dv.y; d[2]=dv.z; d[3]=dv.w;
            }
#pragma unroll
            for (int j = 0; j < 4; j++) {
                int pos = atomicAdd(&g_cnt_q[d[j]], 1);
                if (pos < CAP_Q) g_col_q[(size_t)d[j] * CAP_Q + pos] = s[j];
            }
        }
    } else if (i < R_BASE_CC) {
        // x_emp -> fp16, 4 independent float4 granules per thread (MLP 4)
        long long g = (i - R_BASE_CE) * 4;
        const float4* src = (const float4*)x_emp + g;
        float4 v0 = src[0], v1 = src[1], v2 = src[2], v3 = src[3];
        uint4 o0, o1;
        o0.x = pack_h(v0.x, v0.y); o0.y = pack_h(v0.z, v0.w);
        o0.z = pack_h(v1.x, v1.y); o0.w = pack_h(v1.z, v1.w);
        o1.x = pack_h(v2.x, v2.y); o1.y = pack_h(v2.z, v2.w);
        o1.z = pack_h(v3.x, v3.y); o1.w = pack_h(v3.z, v3.w);
        *(uint4*)&g_xe[g * 2]     = o0;
        *(uint4*)&g_xe[g * 2 + 4] = o1;
    } else if (i < R_BASE_X) {
        long long g = (i - R_BASE_CC) * 4;
        const float4* src = (const float4*)x_con + g;
        float4 v0 = src[0], v1 = src[1], v2 = src[2], v3 = src[3];
        uint4 o0, o1;
        o0.x = pack_h(v0.x, v0.y); o0.y = pack_h(v0.z, v0.w);
        o0.z = pack_h(v1.x, v1.y); o0.w = pack_h(v1.z, v1.w);
        o1.x = pack_h(v2.x, v2.y); o1.y = pack_h(v2.z, v2.w);
        o1.z = pack_h(v3.x, v3.y); o1.w = pack_h(v3.z, v3.w);
        *(uint4*)&g_xc[g * 2]     = o0;
        *(uint4*)&g_xc[g * 2 + 4] = o1;
    } else if (i < R_BASE_T) {
        // x_lic -> A cols [160,288): 4 granules (16 floats) per thread, same row
        long long g = (i - R_BASE_X) * 4;       // float4 granule in x_lic
        int row = (int)(g >> 6);
        int gc  = (int)(g & 63);                // 4-aligned within row (64 granules/row)
        const float4* src = (const float4*)&x_lic[(size_t)row * D_LIC] + gc;
        float4 v0 = src[0], v1 = src[1], v2 = src[2], v3 = src[3];
        uint4 o0, o1;
        o0.x = pack_h(v0.x, v0.y); o0.y = pack_h(v0.z, v0.w);
        o0.z = pack_h(v1.x, v1.y); o0.w = pack_h(v1.z, v1.w);
        o1.x = pack_h(v2.x, v2.y); o1.y = pack_h(v2.z, v2.w);
        o1.z = pack_h(v3.x, v3.y); o1.w = pack_h(v3.z, v3.w);
        size_t o = (size_t)row * KH + 160 + gc * 2;
        *(uint4*)&g_Ah[o]     = o0;
        *(uint4*)&g_Ah[o + 4] = o1;
    } else {
        long long j = i - R_BASE_T;
        if (j < HDIM * KH) {
            int n  = (int)(j / KH);
            int kk = (int)(j % KH);
            float w[2];
#pragma unroll
            for (int t = 0; t < 2; t++) {
                int k = kk * 2 + t;
                if (k < D_EMP)              w[t] = 0.5f * Wl_p[k * HDIM + n];
                else if (k < D_EMP + D_CON) w[t] = 0.5f * Wl_q[(k - D_EMP) * HDIM + n];
                else {
                    int kr = k - (D_EMP + D_CON);
                    w[t] = 0.5f * (Wr_p[kr * HDIM + n] + Wr_q[kr * HDIM + n]);
                }
            }
            g_Wh[j] = pack_h(w[0], w[1]);
        }
        if (j < HDIM) g_b[j] = 0.5f * (b_p[j] + b_q[j]);
    }
}

// ---------------- K2: gather + normalize + pack A; self-cleans counters --------
__global__ void gather_kernel() {
    const int gw = (int)((blockIdx.x * (long long)blockDim.x + threadIdx.x) >> 5);
    const int lane = threadIdx.x & 31;
    if (gw < N_LIC) {
        const int d = gw;
        const int deg = g_cnt_p[d];
        const int degc = min(deg, CAP_P);
        const size_t base = (size_t)d * CAP_P;
        float4 acc = make_float4(0.f, 0.f, 0.f, 0.f);
        int e = 0;
        for (; e + 3 < degc; e += 4) {
            int s0 = g_col_p[base + e],     s1 = g_col_p[base + e + 1];
            int s2 = g_col_p[base + e + 2], s3 = g_col_p[base + e + 3];
            uint2 u0 = *(const uint2*)&g_xe[(size_t)s0 * 64 + lane * 2];
            uint2 u1 = *(const uint2*)&g_xe[(size_t)s1 * 64 + lane * 2];
            uint2 u2 = *(const uint2*)&g_xe[(size_t)s2 * 64 + lane * 2];
            uint2 u3 = *(const uint2*)&g_xe[(size_t)s3 * 64 + lane * 2];
            float2 a0 = unpack_h(u0.x), b0 = unpack_h(u0.y);
            float2 a1 = unpack_h(u1.x), b1 = unpack_h(u1.y);
            float2 a2 = unpack_h(u2.x), b2 = unpack_h(u2.y);
            float2 a3 = unpack_h(u3.x), b3 = unpack_h(u3.y);
            acc.x += (a0.x + a1.x) + (a2.x + a3.x);
            acc.y += (a0.y + a1.y) + (a2.y + a3.y);
            acc.z += (b0.x + b1.x) + (b2.x + b3.x);
            acc.w += (b0.y + b1.y) + (b2.y + b3.y);
        }
        for (; e < degc; e++) {
            int s0 = g_col_p[base + e];
            uint2 u0 = *(const uint2*)&g_xe[(size_t)s0 * 64 + lane * 2];
            float2 a = unpack_h(u0.x), b = unpack_h(u0.y);
            acc.x += a.x; acc.y += a.y; acc.z += b.x; acc.w += b.y;
        }
        if (lane == 0) g_cnt_p[d] = 0;
        float inv = 1.0f / fmaxf((float)deg, 1.0f);
        size_t o = (size_t)d * KH + lane * 2;
        *(uint2*)&g_Ah[o] = make_uint2(pack_h(acc.x * inv, acc.y * inv),
                                       pack_h(acc.z * inv, acc.w * inv));
    } else if (gw < 2 * N_LIC) {
        const int d = gw - N_LIC;
        const int deg = g_cnt_q[d];
        const int degc = min(deg, CAP_Q);
        const size_t base = (size_t)d * CAP_Q;
        float4 a4 = make_float4(0.f, 0.f, 0.f, 0.f);
        float2 a2 = make_float2(0.f, 0.f);
        int e = 0;
        for (; e + 3 < degc; e += 4) {
            int s0 = g_col_q[base + e],     s1 = g_col_q[base + e + 1];
            int s2 = g_col_q[base + e + 2], s3 = g_col_q[base + e + 3];
            const uint32_t* r0 = &g_xc[(size_t)s0 * 96];
            const uint32_t* r1 = &g_xc[(size_t)s1 * 96];
            const uint32_t* r2 = &g_xc[(size_t)s2 * 96];
            const uint32_t* r3 = &g_xc[(size_t)s3 * 96];
            uint2 u0 = *(const uint2*)&r0[lane * 2];
            uint2 u1 = *(const uint2*)&r1[lane * 2];
            uint2 u2 = *(const uint2*)&r2[lane * 2];
            uint2 u3 = *(const uint2*)&r3[lane * 2];
            uint32_t w0 = r0[64 + lane], w1 = r1[64 + lane];
            uint32_t w2 = r2[64 + lane], w3 = r3[64 + lane];
            float2 p0 = unpack_h(u0.x), q0 = unpack_h(u0.y);
            float2 p1 = unpack_h(u1.x), q1 = unpack_h(u1.y);
            float2 p2 = unpack_h(u2.x), q2 = unpack_h(u2.y);
            float2 p3 = unpack_h(u3.x), q3 = unpack_h(u3.y);
            float2 g0 = unpack_h(w0), g1 = unpack_h(w1);
            float2 g2 = unpack_h(w2), g3 = unpack_h(w3);
            a4.x += (p0.x + p1.x) + (p2.x + p3.x);
            a4.y += (p0.y + p1.y) + (p2.y + p3.y);
            a4.z += (q0.x + q1.x) + (q2.x + q3.x);
            a4.w += (q0.y + q1.y) + (q2.y + q3.y);
            a2.x += (g0.x + g1.x) + (g2.x + g3.x);
            a2.y += (g0.y + g1.y) + (g2.y + g3.y);
        }
        for (; e < degc; e++) {
            int s0 = g_col_q[base + e];
            const uint32_t* r0 = &g_xc[(size_t)s0 * 96];
            uint2 u0 = *(const uint2*)&r0[lane * 2];
            uint32_t w0 = r0[64 + lane];
            float2 a = unpack_h(u0.x), b = unpack_h(u0.y);
            float2 g = unpack_h(w0);
            a4.x += a.x; a4.y += a.y; a4.z += b.x; a4.w += b.y;
            a2.x += g.x; a2.y += g.y;
        }
        if (lane == 0) g_cnt_q[d] = 0;
        float inv = 1.0f / fmaxf((float)deg, 1.0f);
        size_t o = (size_t)d * KH + 64 + lane * 2;
        *(uint2*)&g_Ah[o] = make_uint2(pack_h(a4.x * inv, a4.y * inv),
                                       pack_h(a4.z * inv, a4.w * inv));
        g_Ah[(size_t)d * KH + 128 + lane] = pack_h(a2.x * inv, a2.y * inv);
    }
}

// ---------------- K3: fp16 tensor GEMM + bias + relu (64x256 tile, BK=64) -----
#define ASTR 144u
#define BOFF 9216u
#define STG  46080u
#define GEMM_SMEM (2 * 46080)

__global__ __launch_bounds__(256, 2)
void gemm_mma_kernel(float* __restrict__ out) {
    extern __shared__ uint32_t sm[];
    const uint32_t smb = smem_u32(sm);

    const int tid    = threadIdx.x;
    const int lane   = tid & 31;
    const int wid    = tid >> 5;
    const int warp_m = wid & 1;
    const int warp_n = wid >> 1;
    const int m0     = blockIdx.x * 64;

    const int lrow8 = (lane & 7) + ((lane >> 3) & 1) * 8;
    const int lk    = ((lane >> 4) & 1) * 16;
    const uint32_t aoff = (uint32_t)(warp_m * 32 + lrow8) * ASTR + lk;
    const uint32_t boff = BOFF + (uint32_t)(warp_n * 64 + lrow8) * ASTR + lk;

    const int ar = tid >> 2, aq = tid & 3;

    float acc[2][8][4];
#pragma unroll
    for (int i = 0; i < 2; i++)
#pragma unroll
        for (int j = 0; j < 8; j++)
#pragma unroll
            for (int l = 0; l < 4; l++) acc[i][j][l] = 0.f;

    {
        size_t abase = (size_t)(m0 + ar) * KH;
        cp16(smb + ar * ASTR + aq * 16,       &g_Ah[abase + aq * 4]);
        cp16(smb + ar * ASTR + (aq + 4) * 16, &g_Ah[abase + (aq + 4) * 4]);
#pragma unroll
        for (int j = 0; j < 8; j++) {
            int idx = j * 256 + tid;
            int r = idx >> 3, p = idx & 7;
            cp16(smb + BOFF + r * ASTR + p * 16, &g_Wh[(size_t)r * KH + p * 4]);
        }
        asm volatile("cp.async.commit_group;" ::: "memory");
    }

    for (int c = 0; c < NCH9; c++) {
        asm volatile("cp.async.wait_group 0;" ::: "memory");
        __syncthreads();

        if (c < NCH9 - 1) {
            const int nx = c + 1;
            uint32_t sb = smb + (nx & 1) * STG;
            size_t abase = (size_t)(m0 + ar) * KH + nx * 32;
            cp16(sb + ar * ASTR + aq * 16,       &g_Ah[abase + aq * 4]);
            cp16(sb + ar * ASTR + (aq + 4) * 16, &g_Ah[abase + (aq + 4) * 4]);
#pragma unroll
            for (int j = 0; j < 8; j++) {
                int idx = j * 256 + tid;
                int r = idx >> 3, p = idx & 7;
                cp16(sb + BOFF + r * ASTR + p * 16,
                     &g_Wh[(size_t)r * KH + nx * 32 + p * 4]);
            }
            asm volatile("cp.async.commit_group;" ::: "memory");
        }

        const uint32_t s0 = smb + (c & 1) * STG;
#pragma unroll
        for (int ks = 0; ks < 4; ks++) {
            uint32_t ah[2][4], bb[4][4];
            ldsm4(s0 + aoff + ks * 32,              ah[0]);
            ldsm4(s0 + aoff + 16 * ASTR + ks * 32,  ah[1]);
#pragma unroll
            for (int g = 0; g < 4; g++)
                ldsm4(s0 + boff + g * (16 * ASTR) + ks * 32, bb[g]);
#pragma unroll
            for (int j = 0; j < 8; j++) {
                uint32_t b0 = bb[j >> 1][j & 1];
                uint32_t b1 = bb[j >> 1][(j & 1) + 2];
                mma_f16(acc[0][j], ah[0], b0, b1);
                mma_f16(acc[1][j], ah[1], b0, b1);
            }
        }
    }

#pragma unroll
    for (int j = 0; j < 8; j++) {
        int col = warp_n * 64 + j * 8 + (lane & 3) * 2;
        float b0 = g_b[col], b1 = g_b[col + 1];
#pragma unroll
        for (int mf = 0; mf < 2; mf++) {
            int row = m0 + warp_m * 32 + mf * 16 + (lane >> 2);
            float2 o0, o1;
            o0.x = fmaxf(acc[mf][j][0] + b0, 0.f);
            o0.y = fmaxf(acc[mf][j][1] + b1, 0.f);
            o1.x = fmaxf(acc[mf][j][2] + b0, 0.f);
            o1.y = fmaxf(acc[mf][j][3] + b1, 0.f);
            *(float2*)&out[(size_t)row * HDIM + col] = o0;
            *(float2*)&out[(size_t)(row + 8) * HDIM + col] = o1;
        }
    }
}

// ---------------- launch (sequential, 3 kernels) -------------------------------
extern "C" void kernel_launch(void* const* d_in, const int* in_sizes, int n_in,
                              void* d_out, int out_size) {
    const float* x_lic = (const float*)d_in[0];
    const float* x_emp = (const float*)d_in[1];
    const float* x_con = (const float*)d_in[2];
    const float* Wl_p  = (const float*)d_in[3];
    const float* Wr_p  = (const float*)d_in[4];
    const float* b_p   = (const float*)d_in[5];
    const float* Wl_q  = (const float*)d_in[6];
    const float* Wr_q  = (const float*)d_in[7];
    const float* b_q   = (const float*)d_in[8];
    const void*  eps   = d_in[9];
    const void*  epd   = d_in[10];
    const void*  eqs   = d_in[11];
    const void*  eqd   = d_in[12];
    float* out = (float*)d_out;

    cudaFuncSetAttribute(gemm_mma_kernel,
                         cudaFuncAttributeMaxDynamicSharedMemorySize, GEMM_SMEM);

    prep_all_kernel<<<(int)((K1_THREADS + 255) / 256), 256>>>(
        x_emp, x_con, x_lic, Wl_p, Wr_p, b_p, Wl_q, Wr_q, b_q,
        eps, epd, eqs, eqd);
    gather_kernel<<<(2 * N_LIC * 32) / 256, 256>>>();
    gemm_mma_kernel<<<N_LIC / 64, 256, GEMM_SMEM>>>(out);
}

// round 15
// speedup vs baseline: 1.7113x; 1.0193x over previous
#include <cuda_runtime.h>
#include <cuda_fp16.h>
#include <cstdint>

#define N_LIC 40000
#define N_EMP 80000
#define N_CON 60000
#define D_LIC 256
#define D_EMP 128
#define D_CON 192
#define HDIM  256
#define E_P   1280000
#define E_Q   640000
#define KTOT  576    // 128 + 192 + 256
#define KH    288    // KTOT/2 packed u32 per row
#define NCH9  9      // k-chunks of 64 halves (32 u32)

#define CAP_P 96     // max degree, relation p (mean 32)
#define CAP_Q 64     // max degree, relation q (mean 16)

// ---------------- scratch (static device globals; no runtime alloc) --------
__device__ uint32_t g_Ah[(size_t)N_LIC * KH];      // A packed fp16x2 (46MB)
__device__ uint32_t g_Wh[(size_t)HDIM * KH];       // W^T packed fp16x2
__device__ uint32_t g_xe[(size_t)N_EMP * 64];      // x_emp fp16 packed (20MB)
__device__ uint32_t g_xc[(size_t)N_CON * 96];      // x_con fp16 packed (23MB)
__device__ float    g_b[HDIM];
__device__ int      g_cnt_p[N_LIC];                // zero-init; self-cleaned by gather
__device__ int      g_cnt_q[N_LIC];
__device__ int      g_col_p[(size_t)N_LIC * CAP_P];
__device__ int      g_col_q[(size_t)N_LIC * CAP_Q];

// ---------------- helpers ------------------------------------------------------
__device__ __forceinline__ uint32_t pack_h(float x, float y) {
    __half2 h = __floats2half2_rn(x, y);
    return *(uint32_t*)&h;
}
__device__ __forceinline__ float2 unpack_h(uint32_t u) {
    return __half22float2(*(__half2*)&u);
}
__device__ __forceinline__ uint32_t smem_u32(const void* p) {
    uint32_t a;
    asm("{ .reg .u64 t; cvta.to.shared.u64 t, %1; cvt.u32.u64 %0, t; }" : "=r"(a) : "l"(p));
    return a;
}
__device__ __forceinline__ void cp16(uint32_t dst, const void* src) {
    asm volatile("cp.async.cg.shared.global [%0], [%1], 16;" :: "r"(dst), "l"(src));
}
__device__ __forceinline__ void ldsm4(uint32_t addr, uint32_t* r) {
    asm volatile("ldmatrix.sync.aligned.m8n8.x4.shared.b16 {%0,%1,%2,%3}, [%4];"
                 : "=r"(r[0]), "=r"(r[1]), "=r"(r[2]), "=r"(r[3]) : "r"(addr));
}
__device__ __forceinline__ void mma_f16(float* c, const uint32_t* a, uint32_t b0, uint32_t b1) {
    asm volatile(
        "mma.sync.aligned.m16n8k16.row.col.f32.f16.f16.f32 "
        "{%0,%1,%2,%3}, {%4,%5,%6,%7}, {%8,%9}, {%0,%1,%2,%3};"
        : "+f"(c[0]), "+f"(c[1]), "+f"(c[2]), "+f"(c[3])
        : "r"(a[0]), "r"(a[1]), "r"(a[2]), "r"(a[3]), "r"(b0), "r"(b1));
}

// ---------------- K1: conv (first) + bucket fill (last) -------------------------
// conv_e [0, 640000): x_emp quads (MLP4)
// conv_c [640000, 1360000): x_con quads (MLP4)
// pad to 1360128 (CTA-aligned), then fill: 2 edges/thread, 3750 CTAs.
#define T_CONV_E  640000LL
#define T_CONV_C  720000LL
#define R_BASE_CC (T_CONV_E)
#define R_BASE_PAD (T_CONV_E + T_CONV_C)               // 1,360,000
#define R_BASE_F  1360128LL                            // CTA-aligned (5313 CTAs)
#define T_FILL    960000LL                             // (E_P+E_Q)/2
#define K1_THREADS (R_BASE_F + T_FILL)                 // 2,320,128 = 9063 CTAs

__global__ void prep_all_kernel(const float* __restrict__ x_emp, const float* __restrict__ x_con,
                                const void* eps, const void* epd,
                                const void* eqs, const void* eqd) {
    long long i = blockIdx.x * (long long)blockDim.x + threadIdx.x;
    if (blockIdx.x >= (int)(R_BASE_F / 256)) {
        // ---- bucket fill (whole CTAs): 2 edges / thread ----
        __shared__ int s_is64;
        if (threadIdx.x < 32) {
            const unsigned int* probe = (const unsigned int*)eps;
            int lane = threadIdx.x;
            int ok = 1;
#pragma unroll
            for (int t = 0; t < 16; t++) ok &= (probe[1 + 2 * (lane + 32 * t)] == 0u);
            ok = __all_sync(0xffffffffu, ok);
            if (lane == 0) s_is64 = ok;
        }
        __syncthreads();
        const int is64 = s_is64;

        long long e = (i - R_BASE_F) * 2;
        if (e < E_P) {
            int s0, s1, d0, d1;
            if (is64) {
                longlong2 sv = ((const longlong2*)eps)[e >> 1];
                longlong2 dv = ((const longlong2*)epd)[e >> 1];
                s0 = (int)sv.x; s1 = (int)sv.y; d0 = (int)dv.x; d1 = (int)dv.y;
            } else {
                int2 sv = ((const int2*)eps)[e >> 1];
                int2 dv = ((const int2*)epd)[e >> 1];
                s0 = sv.x; s1 = sv.y; d0 = dv.x; d1 = dv.y;
            }
            int p0 = atomicAdd(&g_cnt_p[d0], 1);
            int p1 = atomicAdd(&g_cnt_p[d1], 1);
            if (p0 < CAP_P) g_col_p[(size_t)d0 * CAP_P + p0] = s0;
            if (p1 < CAP_P) g_col_p[(size_t)d1 * CAP_P + p1] = s1;
        } else {
            long long k = e - E_P;
            int s0, s1, d0, d1;
            if (is64) {
                longlong2 sv = ((const longlong2*)eqs)[k >> 1];
                longlong2 dv = ((const longlong2*)eqd)[k >> 1];
                s0 = (int)sv.x; s1 = (int)sv.y; d0 = (int)dv.x; d1 = (int)dv.y;
            } else {
                int2 sv = ((const int2*)eqs)[k >> 1];
                int2 dv = ((const int2*)eqd)[k >> 1];
                s0 = sv.x; s1 = sv.y; d0 = dv.x; d1 = dv.y;
            }
            int p0 = atomicAdd(&g_cnt_q[d0], 1);
            int p1 = atomicAdd(&g_cnt_q[d1], 1);
            if (p0 < CAP_Q) g_col_q[(size_t)d0 * CAP_Q + p0] = s0;
            if (p1 < CAP_Q) g_col_q[(size_t)d1 * CAP_Q + p1] = s1;
        }
    } else if (i < R_BASE_CC) {
        long long g = i * 4;
        const float4* src = (const float4*)x_emp + g;
        float4 v0 = src[0], v1 = src[1], v2 = src[2], v3 = src[3];
        uint4 o0, o1;
        o0.x = pack_h(v0.x, v0.y); o0.y = pack_h(v0.z, v0.w);
        o0.z = pack_h(v1.x, v1.y); o0.w = pack_h(v1.z, v1.w);
        o1.x = pack_h(v2.x, v2.y); o1.y = pack_h(v2.z, v2.w);
        o1.z = pack_h(v3.x, v3.y); o1.w = pack_h(v3.z, v3.w);
        *(uint4*)&g_xe[g * 2]     = o0;
        *(uint4*)&g_xe[g * 2 + 4] = o1;
    } else if (i < R_BASE_PAD) {
        long long g = (i - R_BASE_CC) * 4;
        const float4* src = (const float4*)x_con + g;
        float4 v0 = src[0], v1 = src[1], v2 = src[2], v3 = src[3];
        uint4 o0, o1;
        o0.x = pack_h(v0.x, v0.y); o0.y = pack_h(v0.z, v0.w);
        o0.z = pack_h(v1.x, v1.y); o0.w = pack_h(v1.z, v1.w);
        o1.x = pack_h(v2.x, v2.y); o1.y = pack_h(v2.z, v2.w);
        o1.z = pack_h(v3.x, v3.y); o1.w = pack_h(v3.z, v3.w);
        *(uint4*)&g_xc[g * 2]     = o0;
        *(uint4*)&g_xc[g * 2 + 4] = o1;
    }
    // [R_BASE_PAD, R_BASE_F): idle pad (128 threads)
}

// ---------------- K2: gather + xsplit + W-prep (fused ranges) -------------------
#define G_WARPS  2560000LL                  // 2*N_LIC*32 gather threads
#define G_XS     640000LL                   // xsplit quads (MLP4)
#define G_TAIL   ((long long)(HDIM * KH))   // 73,728 W entries (+ bias in low ids)
#define K2_THREADS (G_WARPS + G_XS + G_TAIL) // 3,273,728 = 12788 CTAs exactly

__global__ void gather_kernel(const float* __restrict__ x_lic,
                              const float* __restrict__ Wl_p, const float* __restrict__ Wr_p,
                              const float* __restrict__ b_p,  const float* __restrict__ Wl_q,
                              const float* __restrict__ Wr_q, const float* __restrict__ b_q) {
    const long long i = blockIdx.x * (long long)blockDim.x + threadIdx.x;
    if (i < G_WARPS) {
        const int gw = (int)(i >> 5);
        const int lane = (int)(i & 31);
        if (gw < N_LIC) {
            const int d = gw;
            const int deg = g_cnt_p[d];
            const int degc = min(deg, CAP_P);
            const size_t base = (size_t)d * CAP_P;
            float4 acc = make_float4(0.f, 0.f, 0.f, 0.f);
            int e = 0;
            for (; e + 3 < degc; e += 4) {
                int s0 = g_col_p[base + e],     s1 = g_col_p[base + e + 1];
                int s2 = g_col_p[base + e + 2], s3 = g_col_p[base + e + 3];
                uint2 u0 = *(const uint2*)&g_xe[(size_t)s0 * 64 + lane * 2];
                uint2 u1 = *(const uint2*)&g_xe[(size_t)s1 * 64 + lane * 2];
                uint2 u2 = *(const uint2*)&g_xe[(size_t)s2 * 64 + lane * 2];
                uint2 u3 = *(const uint2*)&g_xe[(size_t)s3 * 64 + lane * 2];
                float2 a0 = unpack_h(u0.x), b0 = unpack_h(u0.y);
                float2 a1 = unpack_h(u1.x), b1 = unpack_h(u1.y);
                float2 a2 = unpack_h(u2.x), b2 = unpack_h(u2.y);
                float2 a3 = unpack_h(u3.x), b3 = unpack_h(u3.y);
                acc.x += (a0.x + a1.x) + (a2.x + a3.x);
                acc.y += (a0.y + a1.y) + (a2.y + a3.y);
                acc.z += (b0.x + b1.x) + (b2.x + b3.x);
                acc.w += (b0.y + b1.y) + (b2.y + b3.y);
            }
            for (; e < degc; e++) {
                int s0 = g_col_p[base + e];
                uint2 u0 = *(const uint2*)&g_xe[(size_t)s0 * 64 + lane * 2];
                float2 a = unpack_h(u0.x), b = unpack_h(u0.y);
                acc.x += a.x; acc.y += a.y; acc.z += b.x; acc.w += b.y;
            }
            if (lane == 0) g_cnt_p[d] = 0;
            float inv = 1.0f / fmaxf((float)deg, 1.0f);
            size_t o = (size_t)d * KH + lane * 2;
            *(uint2*)&g_Ah[o] = make_uint2(pack_h(acc.x * inv, acc.y * inv),
                                           pack_h(acc.z * inv, acc.w * inv));
        } else {
            const int d = gw - N_LIC;
            const int deg = g_cnt_q[d];
            const int degc = min(deg, CAP_Q);
            const size_t base = (size_t)d * CAP_Q;
            float4 a4 = make_float4(0.f, 0.f, 0.f, 0.f);
            float2 a2 = make_float2(0.f, 0.f);
            int e = 0;
            for (; e + 3 < degc; e += 4) {
                int s0 = g_col_q[base + e],     s1 = g_col_q[base + e + 1];
                int s2 = g_col_q[base + e + 2], s3 = g_col_q[base + e + 3];
                const uint32_t* r0 = &g_xc[(size_t)s0 * 96];
                const uint32_t* r1 = &g_xc[(size_t)s1 * 96];
                const uint32_t* r2 = &g_xc[(size_t)s2 * 96];
                const uint32_t* r3 = &g_xc[(size_t)s3 * 96];
                uint2 u0 = *(const uint2*)&r0[lane * 2];
                uint2 u1 = *(const uint2*)&r1[lane * 2];
                uint2 u2 = *(const uint2*)&r2[lane * 2];
                uint2 u3 = *(const uint2*)&r3[lane * 2];
                uint32_t w0 = r0[64 + lane], w1 = r1[64 + lane];
                uint32_t w2 = r2[64 + lane], w3 = r3[64 + lane];
                float2 p0 = unpack_h(u0.x), q0 = unpack_h(u0.y);
                float2 p1 = unpack_h(u1.x), q1 = unpack_h(u1.y);
                float2 p2 = unpack_h(u2.x), q2 = unpack_h(u2.y);
                float2 p3 = unpack_h(u3.x), q3 = unpack_h(u3.y);
                float2 g0 = unpack_h(w0), g1 = unpack_h(w1);
                float2 g2 = unpack_h(w2), g3 = unpack_h(w3);
                a4.x += (p0.x + p1.x) + (p2.x + p3.x);
                a4.y += (p0.y + p1.y) + (p2.y + p3.y);
                a4.z += (q0.x + q1.x) + (q2.x + q3.x);
                a4.w += (q0.y + q1.y) + (q2.y + q3.y);
                a2.x += (g0.x + g1.x) + (g2.x + g3.x);
                a2.y += (g0.y + g1.y) + (g2.y + g3.y);
            }
            for (; e < degc; e++) {
                int s0 = g_col_q[base + e];
                const uint32_t* r0 = &g_xc[(size_t)s0 * 96];
                uint2 u0 = *(const uint2*)&r0[lane * 2];
                uint32_t w0 = r0[64 + lane];
                float2 a = unpack_h(u0.x), b = unpack_h(u0.y);
                float2 g = unpack_h(w0);
                a4.x += a.x; a4.y += a.y; a4.z += b.x; a4.w += b.y;
                a2.x += g.x; a2.y += g.y;
            }
            if (lane == 0) g_cnt_q[d] = 0;
            float inv = 1.0f / fmaxf((float)deg, 1.0f);
            size_t o = (size_t)d * KH + 64 + lane * 2;
            *(uint2*)&g_Ah[o] = make_uint2(pack_h(a4.x * inv, a4.y * inv),
                                           pack_h(a4.z * inv, a4.w * inv));
            g_Ah[(size_t)d * KH + 128 + lane] = pack_h(a2.x * inv, a2.y * inv);
        }
    } else if (i < G_WARPS + G_XS) {
        // x_lic -> A cols [160,288): 4 granules per thread (MLP4)
        long long g = (i - G_WARPS) * 4;
        int row = (int)(g >> 6);
        int gc  = (int)(g & 63);
        const float4* src = (const float4*)&x_lic[(size_t)row * D_LIC] + gc;
        float4 v0 = src[0], v1 = src[1], v2 = src[2], v3 = src[3];
        uint4 o0, o1;
        o0.x = pack_h(v0.x, v0.y); o0.y = pack_h(v0.z, v0.w);
        o0.z = pack_h(v1.x, v1.y); o0.w = pack_h(v1.z, v1.w);
        o1.x = pack_h(v2.x, v2.y); o1.y = pack_h(v2.z, v2.w);
        o1.z = pack_h(v3.x, v3.y); o1.w = pack_h(v3.z, v3.w);
        size_t o = (size_t)row * KH + 160 + gc * 2;
        *(uint4*)&g_Ah[o]     = o0;
        *(uint4*)&g_Ah[o + 4] = o1;
    } else {
        long long j = i - (G_WARPS + G_XS);
        int n  = (int)(j / KH);
        int kk = (int)(j % KH);
        float w[2];
#pragma unroll
        for (int t = 0; t < 2; t++) {
            int k = kk * 2 + t;
            if (k < D_EMP)              w[t] = 0.5f * Wl_p[k * HDIM + n];
            else if (k < D_EMP + D_CON) w[t] = 0.5f * Wl_q[(k - D_EMP) * HDIM + n];
            else {
                int kr = k - (D_EMP + D_CON);
                w[t] = 0.5f * (Wr_p[kr * HDIM + n] + Wr_q[kr * HDIM + n]);
            }
        }
        g_Wh[j] = pack_h(w[0], w[1]);
        if (j < HDIM) g_b[j] = 0.5f * (b_p[j] + b_q[j]);
    }
}

// ---------------- K3: fp16 tensor GEMM + bias + relu (64x256 tile, BK=64) -----
#define ASTR 144u
#define BOFF 9216u
#define STG  46080u
#define GEMM_SMEM (2 * 46080)

__global__ __launch_bounds__(256, 2)
void gemm_mma_kernel(float* __restrict__ out) {
    extern __shared__ uint32_t sm[];
    const uint32_t smb = smem_u32(sm);

    const int tid    = threadIdx.x;
    const int lane   = tid & 31;
    const int wid    = tid >> 5;
    const int warp_m = wid & 1;
    const int warp_n = wid >> 1;
    const int m0     = blockIdx.x * 64;

    const int lrow8 = (lane & 7) + ((lane >> 3) & 1) * 8;
    const int lk    = ((lane >> 4) & 1) * 16;
    const uint32_t aoff = (uint32_t)(warp_m * 32 + lrow8) * ASTR + lk;
    const uint32_t boff = BOFF + (uint32_t)(warp_n * 64 + lrow8) * ASTR + lk;

    const int ar = tid >> 2, aq = tid & 3;

    float acc[2][8][4];
#pragma unroll
    for (int i = 0; i < 2; i++)
#pragma unroll
        for (int j = 0; j < 8; j++)
#pragma unroll
            for (int l = 0; l < 4; l++) acc[i][j][l] = 0.f;

    {
        size_t abase = (size_t)(m0 + ar) * KH;
        cp16(smb + ar * ASTR + aq * 16,       &g_Ah[abase + aq * 4]);
        cp16(smb + ar * ASTR + (aq + 4) * 16, &g_Ah[abase + (aq + 4) * 4]);
#pragma unroll
        for (int j = 0; j < 8; j++) {
            int idx = j * 256 + tid;
            int r = idx >> 3, p = idx & 7;
            cp16(smb + BOFF + r * ASTR + p * 16, &g_Wh[(size_t)r * KH + p * 4]);
        }
        asm volatile("cp.async.commit_group;" ::: "memory");
    }

    for (int c = 0; c < NCH9; c++) {
        asm volatile("cp.async.wait_group 0;" ::: "memory");
        __syncthreads();

        if (c < NCH9 - 1) {
            const int nx = c + 1;
            uint32_t sb = smb + (nx & 1) * STG;
            size_t abase = (size_t)(m0 + ar) * KH + nx * 32;
            cp16(sb + ar * ASTR + aq * 16,       &g_Ah[abase + aq * 4]);
            cp16(sb + ar * ASTR + (aq + 4) * 16, &g_Ah[abase + (aq + 4) * 4]);
#pragma unroll
            for (int j = 0; j < 8; j++) {
                int idx = j * 256 + tid;
                int r = idx >> 3, p = idx & 7;
                cp16(sb + BOFF + r * ASTR + p * 16,
                     &g_Wh[(size_t)r * KH + nx * 32 + p * 4]);
            }
            asm volatile("cp.async.commit_group;" ::: "memory");
        }

        const uint32_t s0 = smb + (c & 1) * STG;
#pragma unroll
        for (int ks = 0; ks < 4; ks++) {
            uint32_t ah[2][4], bb[4][4];
            ldsm4(s0 + aoff + ks * 32,              ah[0]);
            ldsm4(s0 + aoff + 16 * ASTR + ks * 32,  ah[1]);
#pragma unroll
            for (int g = 0; g < 4; g++)
                ldsm4(s0 + boff + g * (16 * ASTR) + ks * 32, bb[g]);
#pragma unroll
            for (int j = 0; j < 8; j++) {
                uint32_t b0 = bb[j >> 1][j & 1];
                uint32_t b1 = bb[j >> 1][(j & 1) + 2];
                mma_f16(acc[0][j], ah[0], b0, b1);
                mma_f16(acc[1][j], ah[1], b0, b1);
            }
        }
    }

#pragma unroll
    for (int j = 0; j < 8; j++) {
        int col = warp_n * 64 + j * 8 + (lane & 3) * 2;
        float b0 = g_b[col], b1 = g_b[col + 1];
#pragma unroll
        for (int mf = 0; mf < 2; mf++) {
            int row = m0 + warp_m * 32 + mf * 16 + (lane >> 2);
            float2 o0, o1;
            o0.x = fmaxf(acc[mf][j][0] + b0, 0.f);
            o0.y = fmaxf(acc[mf][j][1] + b1, 0.f);
            o1.x = fmaxf(acc[mf][j][2] + b0, 0.f);
            o1.y = fmaxf(acc[mf][j][3] + b1, 0.f);
            *(float2*)&out[(size_t)row * HDIM + col] = o0;
            *(float2*)&out[(size_t)(row + 8) * HDIM + col] = o1;
        }
    }
}

// ---------------- launch (sequential, 3 kernels) -------------------------------
extern "C" void kernel_launch(void* const* d_in, const int* in_sizes, int n_in,
                              void* d_out, int out_size) {
    const float* x_lic = (const float*)d_in[0];
    const float* x_emp = (const float*)d_in[1];
    const float* x_con = (const float*)d_in[2];
    const float* Wl_p  = (const float*)d_in[3];
    const float* Wr_p  = (const float*)d_in[4];
    const float* b_p   = (const float*)d_in[5];
    const float* Wl_q  = (const float*)d_in[6];
    const float* Wr_q  = (const float*)d_in[7];
    const float* b_q   = (const float*)d_in[8];
    const void*  eps   = d_in[9];
    const void*  epd   = d_in[10];
    const void*  eqs   = d_in[11];
    const void*  eqd   = d_in[12];
    float* out = (float*)d_out;

    cudaFuncSetAttribute(gemm_mma_kernel,
                         cudaFuncAttributeMaxDynamicSharedMemorySize, GEMM_SMEM);

    prep_all_kernel<<<(int)(K1_THREADS / 256), 256>>>(x_emp, x_con, eps, epd, eqs, eqd);
    gather_kernel<<<(int)(K2_THREADS / 256), 256>>>(x_lic, Wl_p, Wr_p, b_p, Wl_q, Wr_q, b_q);
    gemm_mma_kernel<<<N_LIC / 64, 256, GEMM_SMEM>>>(out);
}